// round 3
// baseline (speedup 1.0000x reference)
#include <cuda_runtime.h>
#include <math.h>

// Problem constants
#define LAYERS 8
#define BATCH  256
#define TIME   8
#define EDIM   1024
#define HDIM   1024
#define KDIM   2048   // EDIM + HDIM

// Tiling
#define BM 128   // batch rows per block
#define BJ 16    // hidden columns per block (per gate; block computes 4 gates)
#define BK 16    // k-slice

// Scratch: ping-pong per-layer outputs (T,B,H) + running cell state (B,H)
__device__ float g_buf0[TIME * BATCH * HDIM];
__device__ float g_buf1[TIME * BATCH * HDIM];
__device__ float g_crun[BATCH * HDIM];

__global__ __launch_bounds__(256, 1)
void lstm_step_kernel(
    const float* __restrict__ inA, int strideA,      // input rows: (B x E), row stride strideA
    const float* __restrict__ hprev,                 // (B x H), row stride H
    const float* __restrict__ Wu, const float* __restrict__ Wf,
    const float* __restrict__ Wo, const float* __restrict__ Wc,  // each (K2 x H) row-major
    const float* __restrict__ bu, const float* __restrict__ bf,
    const float* __restrict__ bo, const float* __restrict__ bc,  // each (H)
    const float* __restrict__ c_old_src,             // c0[l] (t==0) or g_crun
    float* __restrict__ c_run,                       // (B x H)
    float* __restrict__ h_out,                       // cur[t] (B x H)
    float* __restrict__ outH,                        // base + t*H (stride T*H) or null
    float* __restrict__ outC,                        // base + t*H (stride T*H) or null
    float* __restrict__ outHt,                       // (B x H) or null
    float* __restrict__ outCt)                       // (B x H) or null
{
    __shared__ float zs[BK][BM];        // z tile [k][b]
    __shared__ float ws[4][BK][BJ];     // weights [gate][k][j]

    const int tid = threadIdx.x;
    const int tx = tid & 15;            // j within tile
    const int ty = tid >> 4;            // row group
    const int j0 = blockIdx.x * BJ;
    const int b0 = blockIdx.y * BM;

    float acc[4][8];
    #pragma unroll
    for (int g = 0; g < 4; g++)
        #pragma unroll
        for (int r = 0; r < 8; r++)
            acc[g][r] = 0.0f;

    #pragma unroll 1
    for (int k0 = 0; k0 < KDIM; k0 += BK) {
        // Load z tile: 128 rows x 16 k, thread (ty,tx) -> rows ty+16r, k=tx
        {
            const int gk = k0 + tx;
            if (gk < EDIM) {
                #pragma unroll
                for (int r = 0; r < 8; r++) {
                    const int b = b0 + ty + r * 16;
                    zs[tx][ty + r * 16] = inA[(size_t)b * strideA + gk];
                }
            } else {
                const int hk = gk - EDIM;
                #pragma unroll
                for (int r = 0; r < 8; r++) {
                    const int b = b0 + ty + r * 16;
                    zs[tx][ty + r * 16] = hprev[(size_t)b * HDIM + hk];
                }
            }
        }
        // Load weight tiles: 4 gates x 16 k x 16 j = 1024 floats, 4 per thread
        {
            #pragma unroll
            for (int i = 0; i < 4; i++) {
                const int e  = tid + i * 256;
                const int g  = e >> 8;
                const int kk = (e >> 4) & 15;
                const int jj = e & 15;
                const float* W = (g == 0) ? Wu : (g == 1) ? Wf : (g == 2) ? Wo : Wc;
                ws[g][kk][jj] = W[(size_t)(k0 + kk) * HDIM + (j0 + jj)];
            }
        }
        __syncthreads();

        #pragma unroll
        for (int kk = 0; kk < BK; kk++) {
            const float w0 = ws[0][kk][tx];
            const float w1 = ws[1][kk][tx];
            const float w2 = ws[2][kk][tx];
            const float w3 = ws[3][kk][tx];
            #pragma unroll
            for (int r = 0; r < 8; r++) {
                const float z = zs[kk][ty + r * 16];
                acc[0][r] = fmaf(z, w0, acc[0][r]);
                acc[1][r] = fmaf(z, w1, acc[1][r]);
                acc[2][r] = fmaf(z, w2, acc[2][r]);
                acc[3][r] = fmaf(z, w3, acc[3][r]);
            }
        }
        __syncthreads();
    }

    // Epilogue: LSTM cell update, fused
    const int j = j0 + tx;
    const float b_u = bu[j], b_f = bf[j], b_o = bo[j], b_c = bc[j];

    #pragma unroll
    for (int r = 0; r < 8; r++) {
        const int b = b0 + ty + r * 16;
        const size_t idx = (size_t)b * HDIM + j;
        const float u  = 1.0f / (1.0f + expf(-(acc[0][r] + b_u)));
        const float f  = 1.0f / (1.0f + expf(-(acc[1][r] + b_f)));
        const float o  = 1.0f / (1.0f + expf(-(acc[2][r] + b_o)));
        const float ct = tanhf(acc[3][r] + b_c);
        const float c_old = c_old_src[idx];
        const float c_new = f * c_old + u * ct;
        const float h_new = o * tanhf(c_new);
        c_run[idx] = c_new;
        h_out[idx] = h_new;
        if (outH) {
            const size_t oidx = (size_t)b * (TIME * HDIM) + j;  // outH already offset by t*H
            outH[oidx] = h_new;
            outC[oidx] = c_new;
            if (outHt) {
                outHt[idx] = h_new;
                outCt[idx] = c_new;
            }
        }
    }
}

extern "C" void kernel_launch(void* const* d_in, const int* in_sizes, int n_in,
                              void* d_out, int out_size) {
    const float* x  = (const float*)d_in[0];   // (B, T, E)
    const float* h0 = (const float*)d_in[1];   // (L, B, H)
    const float* c0 = (const float*)d_in[2];   // (L, B, H)
    const float* Wu = (const float*)d_in[3];   // (L, K2, H)
    const float* bu = (const float*)d_in[4];   // (L, H)
    const float* Wf = (const float*)d_in[5];
    const float* bf = (const float*)d_in[6];
    const float* Wo = (const float*)d_in[7];
    const float* bo = (const float*)d_in[8];
    const float* Wc = (const float*)d_in[9];
    const float* bc = (const float*)d_in[10];

    float* out = (float*)d_out;
    float* outHidden = out;                                        // (B, T, H)
    float* outMem    = out + (size_t)BATCH * TIME * HDIM;          // (B, T, H)
    float* outHt     = out + (size_t)2 * BATCH * TIME * HDIM;      // (B, 1, H)
    float* outCt     = outHt + (size_t)BATCH * HDIM;               // (B, 1, H)

    float *buf0, *buf1, *crun;
    cudaGetSymbolAddress((void**)&buf0, g_buf0);
    cudaGetSymbolAddress((void**)&buf1, g_buf1);
    cudaGetSymbolAddress((void**)&crun, g_crun);

    const dim3 grid(HDIM / BJ, BATCH / BM);  // (64, 2)
    const dim3 block(256);

    // Layer-outer, time-inner: keeps one layer's 32 MB of weights L2-resident
    // across all 8 timesteps.
    for (int l = 0; l < LAYERS; l++) {
        const size_t wOff = (size_t)l * KDIM * HDIM;
        const size_t bOff = (size_t)l * HDIM;
        const float* Wu_l = Wu + wOff;
        const float* Wf_l = Wf + wOff;
        const float* Wo_l = Wo + wOff;
        const float* Wc_l = Wc + wOff;
        const float* bu_l = bu + bOff;
        const float* bf_l = bf + bOff;
        const float* bo_l = bo + bOff;
        const float* bc_l = bc + bOff;

        float* cur        = (l & 1) ? buf1 : buf0;
        const float* prev = (l & 1) ? buf0 : buf1;
        const bool last = (l == LAYERS - 1);

        for (int t = 0; t < TIME; t++) {
            const float* inA;
            int strideA;
            if (l == 0) {
                inA = x + (size_t)t * EDIM;      // x[b][t][:] with row stride T*E
                strideA = TIME * EDIM;
            } else {
                inA = prev + (size_t)t * BATCH * HDIM;
                strideA = HDIM;
            }
            const float* hprev = (t == 0) ? (h0 + (size_t)l * BATCH * HDIM)
                                          : (cur + (size_t)(t - 1) * BATCH * HDIM);
            const float* coldsrc = (t == 0) ? (c0 + (size_t)l * BATCH * HDIM) : crun;
            float* hout = cur + (size_t)t * BATCH * HDIM;

            float* oH  = last ? (outHidden + (size_t)t * HDIM) : nullptr;
            float* oC  = last ? (outMem + (size_t)t * HDIM) : nullptr;
            float* oHt = (last && t == TIME - 1) ? outHt : nullptr;
            float* oCt = (last && t == TIME - 1) ? outCt : nullptr;

            lstm_step_kernel<<<grid, block>>>(
                inA, strideA, hprev,
                Wu_l, Wf_l, Wo_l, Wc_l,
                bu_l, bf_l, bo_l, bc_l,
                coldsrc, crun, hout,
                oH, oC, oHt, oCt);
        }
    }
}

// round 4
// speedup vs baseline: 3.4927x; 3.4927x over previous
#include <cuda_runtime.h>
#include <math.h>
#include <stdint.h>

// Problem constants
#define LAYERS 8
#define BATCH  256
#define TIME   8
#define EDIM   1024
#define HDIM   1024
#define KDIM   2048   // EDIM + HDIM

// Tiling
#define BM  64        // batch rows per block
#define BJG 32        // hidden cols per gate per block (block does 4 gates -> 128 cols)
#define BK  32        // k-slice per stage
#define NCHUNK (KDIM / BK)   // 64

// Scratch: ping-pong per-layer outputs (T,B,H) + running cell state (B,H)
__device__ float g_buf0[TIME * BATCH * HDIM];
__device__ float g_buf1[TIME * BATCH * HDIM];
__device__ float g_crun[BATCH * HDIM];

__device__ __forceinline__ uint32_t f2tf32(float f) {
    uint32_t r;
    asm("cvt.rna.tf32.f32 %0, %1;" : "=r"(r) : "f"(f));
    return r;
}

__device__ __forceinline__ void mma_tf32(float c[4],
                                         uint32_t a0, uint32_t a1, uint32_t a2, uint32_t a3,
                                         uint32_t b0, uint32_t b1) {
    asm volatile(
        "mma.sync.aligned.m16n8k8.row.col.f32.tf32.tf32.f32 "
        "{%0,%1,%2,%3}, {%4,%5,%6,%7}, {%8,%9}, {%0,%1,%2,%3};"
        : "+f"(c[0]), "+f"(c[1]), "+f"(c[2]), "+f"(c[3])
        : "r"(a0), "r"(a1), "r"(a2), "r"(a3), "r"(b0), "r"(b1));
}

// Smem per stage: A tile 64x32 in [k/4][m][k%4] layout (2048 floats)
//                 B tiles 4 gates x 32x32 in [k/4][n][k%4] layout (4096 floats)
// Two stages = 12288 floats = 48KB. Epilogue gate-exchange buffer (64x130) aliases it.
#define STAGE_FLOATS 6144
#define SB_OFF       2048
#define GS_STRIDE    130

__global__ __launch_bounds__(256, 1)
void lstm_step_mma(
    const float* __restrict__ inA, int strideA,      // (B x E) rows, row stride strideA
    const float* __restrict__ hprev,                 // (B x H)
    const float* __restrict__ Wu, const float* __restrict__ Wf,
    const float* __restrict__ Wo, const float* __restrict__ Wc,  // each (K2 x H) row-major
    const float* __restrict__ bu, const float* __restrict__ bf,
    const float* __restrict__ bo, const float* __restrict__ bc,
    const float* __restrict__ c_old_src,
    float* __restrict__ c_run,
    float* __restrict__ h_out,
    float* __restrict__ outH,        // base + t*H (row stride T*H) or null
    float* __restrict__ outC,
    float* __restrict__ outHt,
    float* __restrict__ outCt)
{
    __shared__ float smem[2 * STAGE_FLOATS];

    const int tid  = threadIdx.x;
    const int lane = tid & 31;
    const int warp = tid >> 5;
    const int wy   = warp >> 2;        // 0..1 : row half
    const int wx   = warp & 3;         // 0..3 : gate
    const int g4   = lane >> 2;        // groupID
    const int t4   = lane & 3;         // threadID in group
    const int j0   = blockIdx.x * BJG;
    const int b0   = blockIdx.y * BM;

    // Global-load thread mapping
    const int tA_m = tid >> 2;          // 0..63
    const int tA_k = (tid & 3) * 8;     // 0,8,16,24
    const int tB_k = tid >> 3;          // 0..31
    const int tB_j = (tid & 7) * 4;     // 0..28

    float acc[2][4][4];
    #pragma unroll
    for (int mi = 0; mi < 2; mi++)
        #pragma unroll
        for (int ni = 0; ni < 4; ni++)
            #pragma unroll
            for (int r = 0; r < 4; r++)
                acc[mi][ni][r] = 0.0f;

    float4 pA0, pA1, pW0, pW1, pW2, pW3;

    auto load_global = [&](int c) {
        const int k0 = c * BK;
        const float* aSrc;
        if (k0 < EDIM)
            aSrc = inA + (size_t)(b0 + tA_m) * strideA + (k0 + tA_k);
        else
            aSrc = hprev + (size_t)(b0 + tA_m) * HDIM + (k0 - EDIM + tA_k);
        pA0 = *(const float4*)aSrc;
        pA1 = *(const float4*)(aSrc + 4);
        const size_t wOff = (size_t)(k0 + tB_k) * HDIM + (j0 + tB_j);
        pW0 = *(const float4*)(Wu + wOff);
        pW1 = *(const float4*)(Wf + wOff);
        pW2 = *(const float4*)(Wo + wOff);
        pW3 = *(const float4*)(Wc + wOff);
    };

    auto store_smem = [&](int s) {
        float* sA = smem + s * STAGE_FLOATS;
        float* sB = sA + SB_OFF;
        // A: two float4 stores into [k/4][m][k%4]
        const int aIdx = (tA_k >> 2) * 256 + tA_m * 4;
        uint4 u0 = make_uint4(f2tf32(pA0.x), f2tf32(pA0.y), f2tf32(pA0.z), f2tf32(pA0.w));
        uint4 u1 = make_uint4(f2tf32(pA1.x), f2tf32(pA1.y), f2tf32(pA1.z), f2tf32(pA1.w));
        *(uint4*)(sA + aIdx)       = u0;
        *(uint4*)(sA + aIdx + 256) = u1;
        // B: scatter (stride 4 between consecutive n)
        const int bBase = (tB_k >> 2) * 128 + tB_j * 4 + (tB_k & 3);
        #define STG(gi, v)                                                     \
            sB[(gi)*1024 + bBase +  0] = __uint_as_float(f2tf32((v).x));       \
            sB[(gi)*1024 + bBase +  4] = __uint_as_float(f2tf32((v).y));       \
            sB[(gi)*1024 + bBase +  8] = __uint_as_float(f2tf32((v).z));       \
            sB[(gi)*1024 + bBase + 12] = __uint_as_float(f2tf32((v).w));
        STG(0, pW0) STG(1, pW1) STG(2, pW2) STG(3, pW3)
        #undef STG
    };

    const int aOff = (32 * wy + g4) * 4 + t4;
    const int bOff = wx * 1024 + g4 * 4 + t4;

    auto compute = [&](int s) {
        const float* sA = smem + s * STAGE_FLOATS;
        const float* sB = sA + SB_OFF;
        #pragma unroll
        for (int q = 0; q < 4; q++) {
            uint32_t a[2][4];
            #pragma unroll
            for (int mi = 0; mi < 2; mi++) {
                const int base = aOff + 512 * q + 64 * mi;
                a[mi][0] = __float_as_uint(sA[base]);
                a[mi][1] = __float_as_uint(sA[base + 32]);
                a[mi][2] = __float_as_uint(sA[base + 256]);
                a[mi][3] = __float_as_uint(sA[base + 288]);
            }
            #pragma unroll
            for (int ni = 0; ni < 4; ni++) {
                const int bb = bOff + 256 * q + 32 * ni;
                const uint32_t bb0 = __float_as_uint(sB[bb]);
                const uint32_t bb1 = __float_as_uint(sB[bb + 128]);
                mma_tf32(acc[0][ni], a[0][0], a[0][1], a[0][2], a[0][3], bb0, bb1);
                mma_tf32(acc[1][ni], a[1][0], a[1][1], a[1][2], a[1][3], bb0, bb1);
            }
        }
    };

    // Pipelined main loop
    load_global(0);
    store_smem(0);
    __syncthreads();

    #pragma unroll 1
    for (int c = 0; c < NCHUNK; c++) {
        const int s = c & 1;
        if (c + 1 < NCHUNK) load_global(c + 1);
        compute(s);
        if (c + 1 < NCHUNK) {
            __syncthreads();
            store_smem(s ^ 1);
            __syncthreads();
        }
    }

    // Epilogue: exchange gates through smem, fused cell update
    __syncthreads();
    float* gs = smem;   // 64 x 130
    #pragma unroll
    for (int mi = 0; mi < 2; mi++) {
        #pragma unroll
        for (int ni = 0; ni < 4; ni++) {
            const int row = 32 * wy + 16 * mi + g4;
            const int col = wx * 32 + ni * 8 + t4 * 2;
            *(float2*)(gs + row * GS_STRIDE + col) =
                make_float2(acc[mi][ni][0], acc[mi][ni][1]);
            *(float2*)(gs + (row + 8) * GS_STRIDE + col) =
                make_float2(acc[mi][ni][2], acc[mi][ni][3]);
        }
    }
    __syncthreads();

    const int jj = tid & 31;
    const int r0 = tid >> 5;
    const int j  = j0 + jj;
    const float b_u = bu[j], b_f = bf[j], b_o = bo[j], b_c = bc[j];

    #pragma unroll
    for (int i = 0; i < 8; i++) {
        const int row = r0 + 8 * i;
        const int b   = b0 + row;
        const size_t idx = (size_t)b * HDIM + j;
        const float u  = 1.0f / (1.0f + expf(-(gs[row * GS_STRIDE +       jj] + b_u)));
        const float f  = 1.0f / (1.0f + expf(-(gs[row * GS_STRIDE + 32 + jj] + b_f)));
        const float o  = 1.0f / (1.0f + expf(-(gs[row * GS_STRIDE + 64 + jj] + b_o)));
        const float ct = tanhf(gs[row * GS_STRIDE + 96 + jj] + b_c);
        const float c_old = c_old_src[idx];
        const float c_new = f * c_old + u * ct;
        const float h_new = o * tanhf(c_new);
        c_run[idx] = c_new;
        h_out[idx] = h_new;
        if (outH) {
            const size_t oidx = (size_t)b * (TIME * HDIM) + j;
            outH[oidx] = h_new;
            outC[oidx] = c_new;
            if (outHt) {
                outHt[idx] = h_new;
                outCt[idx] = c_new;
            }
        }
    }
}

extern "C" void kernel_launch(void* const* d_in, const int* in_sizes, int n_in,
                              void* d_out, int out_size) {
    const float* x  = (const float*)d_in[0];   // (B, T, E)
    const float* h0 = (const float*)d_in[1];   // (L, B, H)
    const float* c0 = (const float*)d_in[2];   // (L, B, H)
    const float* Wu = (const float*)d_in[3];   // (L, K2, H)
    const float* bu = (const float*)d_in[4];   // (L, H)
    const float* Wf = (const float*)d_in[5];
    const float* bf = (const float*)d_in[6];
    const float* Wo = (const float*)d_in[7];
    const float* bo = (const float*)d_in[8];
    const float* Wc = (const float*)d_in[9];
    const float* bc = (const float*)d_in[10];

    float* out = (float*)d_out;
    float* outHidden = out;                                        // (B, T, H)
    float* outMem    = out + (size_t)BATCH * TIME * HDIM;          // (B, T, H)
    float* outHt     = out + (size_t)2 * BATCH * TIME * HDIM;      // (B, 1, H)
    float* outCt     = outHt + (size_t)BATCH * HDIM;               // (B, 1, H)

    float *buf0, *buf1, *crun;
    cudaGetSymbolAddress((void**)&buf0, g_buf0);
    cudaGetSymbolAddress((void**)&buf1, g_buf1);
    cudaGetSymbolAddress((void**)&crun, g_crun);

    const dim3 grid(HDIM / BJG, BATCH / BM);  // (32, 4) = 128 blocks
    const dim3 block(256);

    // Layer-outer, time-inner: keeps one layer's 32 MB of weights L2-resident
    // across all 8 timesteps.
    for (int l = 0; l < LAYERS; l++) {
        const size_t wOff = (size_t)l * KDIM * HDIM;
        const size_t bOff = (size_t)l * HDIM;
        const float* Wu_l = Wu + wOff;
        const float* Wf_l = Wf + wOff;
        const float* Wo_l = Wo + wOff;
        const float* Wc_l = Wc + wOff;
        const float* bu_l = bu + bOff;
        const float* bf_l = bf + bOff;
        const float* bo_l = bo + bOff;
        const float* bc_l = bc + bOff;

        float* cur        = (l & 1) ? buf1 : buf0;
        const float* prev = (l & 1) ? buf0 : buf1;
        const bool last = (l == LAYERS - 1);

        for (int t = 0; t < TIME; t++) {
            const float* inA;
            int strideA;
            if (l == 0) {
                inA = x + (size_t)t * EDIM;      // x[b][t][:] with row stride T*E
                strideA = TIME * EDIM;
            } else {
                inA = prev + (size_t)t * BATCH * HDIM;
                strideA = HDIM;
            }
            const float* hprev = (t == 0) ? (h0 + (size_t)l * BATCH * HDIM)
                                          : (cur + (size_t)(t - 1) * BATCH * HDIM);
            const float* coldsrc = (t == 0) ? (c0 + (size_t)l * BATCH * HDIM) : crun;
            float* hout = cur + (size_t)t * BATCH * HDIM;

            float* oH  = last ? (outHidden + (size_t)t * HDIM) : nullptr;
            float* oC  = last ? (outMem + (size_t)t * HDIM) : nullptr;
            float* oHt = (last && t == TIME - 1) ? outHt : nullptr;
            float* oCt = (last && t == TIME - 1) ? outCt : nullptr;

            lstm_step_mma<<<grid, block>>>(
                inA, strideA, hprev,
                Wu_l, Wf_l, Wo_l, Wc_l,
                bu_l, bf_l, bo_l, bc_l,
                coldsrc, crun, hout,
                oH, oC, oHt, oCt);
        }
    }
}